// round 3
// baseline (speedup 1.0000x reference)
#include <cuda_runtime.h>

// Problem shape (fixed by setup_inputs):
//   x1: [B=32, C=64, h=42, w=42]       float32
//   x2: [B=32, S=25, C=64, h=42, w=42] float32
//   out: [B, S*h*w] = [32, 44100]      float32
// out[b, s*HW + p] = sqrt( sum_c (x1[b,c,p] - x2[b,s,c,p])^2 )

#define B_  32
#define S_  25
#define C_  64
#define HW_ 1764          // 42*42
#define HW4_ 441          // HW/4 (exact)
#define TOTAL_ (B_ * S_ * HW4_)   // 352800 work items (one float4 output each)

// GB300: 152 SMs, 3 CTAs/SM at 80ish regs -> exact-residency persistent grid.
#define GRID_  (152 * 3)
#define BLOCK_ 256

__global__ __launch_bounds__(BLOCK_, 3)
void euclidean_block_kernel(const float* __restrict__ x1,
                            const float* __restrict__ x2,
                            float* __restrict__ out) {
    const int stride = GRID_ * BLOCK_;

    for (int t = blockIdx.x * BLOCK_ + threadIdx.x; t < TOTAL_; t += stride) {
        int p4 = t % HW4_;          // which float4 within the 1764-pixel plane
        int bs = t / HW4_;          // (b*S + s)
        int b  = bs / S_;

        const float4* __restrict__ x1p =
            reinterpret_cast<const float4*>(x1 + (size_t)b * C_ * HW_) + p4;
        const float4* __restrict__ x2p =
            reinterpret_cast<const float4*>(x2 + (size_t)bs * C_ * HW_) + p4;

        float ax = 0.f, ay = 0.f, az = 0.f, aw = 0.f;

        // 8 channels per batch: 16 independent float4 loads in flight
        // before any consumption -> MLP ~16 per thread.
        #pragma unroll
        for (int cb = 0; cb < C_; cb += 8) {
            float4 a[8], v[8];
            #pragma unroll
            for (int i = 0; i < 8; ++i) {
                a[i] = x1p[(cb + i) * HW4_];
            }
            #pragma unroll
            for (int i = 0; i < 8; ++i) {
                v[i] = __ldcs(&x2p[(cb + i) * HW4_]);   // streaming: evict-first
            }
            #pragma unroll
            for (int i = 0; i < 8; ++i) {
                float d0 = a[i].x - v[i].x;
                float d1 = a[i].y - v[i].y;
                float d2 = a[i].z - v[i].z;
                float d3 = a[i].w - v[i].w;
                ax = fmaf(d0, d0, ax);
                ay = fmaf(d1, d1, ay);
                az = fmaf(d2, d2, az);
                aw = fmaf(d3, d3, aw);
            }
        }

        float4 r;
        r.x = sqrtf(ax);
        r.y = sqrtf(ay);
        r.z = sqrtf(az);
        r.w = sqrtf(aw);

        reinterpret_cast<float4*>(out)[(size_t)bs * HW4_ + p4] = r;
    }
}

extern "C" void kernel_launch(void* const* d_in, const int* in_sizes, int n_in,
                              void* d_out, int out_size) {
    const float* x1 = (const float*)d_in[0];
    const float* x2 = (const float*)d_in[1];
    float* out = (float*)d_out;

    euclidean_block_kernel<<<GRID_, BLOCK_>>>(x1, x2, out);
}

// round 4
// speedup vs baseline: 1.0289x; 1.0289x over previous
#include <cuda_runtime.h>

// Problem shape (fixed by setup_inputs):
//   x1: [B=32, C=64, h=42, w=42]       float32
//   x2: [B=32, S=25, C=64, h=42, w=42] float32
//   out: [B, S*h*w] = [32, 44100]      float32
// out[b, s*HW + p] = sqrt( sum_c (x1[b,c,p] - x2[b,s,c,p])^2 )

#define B_  32
#define S_  25
#define C_  64
#define HW_ 1764          // 42*42
#define HW4_ 441          // HW/4 (exact)
#define TOTAL_ (B_ * S_ * HW4_)   // 352800 threads, one float4 output each

#define CB_ 4                      // channels per pipeline stage
#define NSTAGE_ (C_ / CB_)         // 16 stages

__global__ __launch_bounds__(256, 3)
void euclidean_block_kernel(const float* __restrict__ x1,
                            const float* __restrict__ x2,
                            float* __restrict__ out) {
    int t = blockIdx.x * blockDim.x + threadIdx.x;
    if (t >= TOTAL_) return;

    int p4 = t % HW4_;          // which float4 within the 1764-pixel plane
    int bs = t / HW4_;          // (b*S + s)
    int b  = bs / S_;

    const float4* __restrict__ x1p =
        reinterpret_cast<const float4*>(x1 + (size_t)b * C_ * HW_) + p4;
    const float4* __restrict__ x2p =
        reinterpret_cast<const float4*>(x2 + (size_t)bs * C_ * HW_) + p4;

    float ax = 0.f, ay = 0.f, az = 0.f, aw = 0.f;

    // Double-buffered register pipeline: while consuming stage s, stage s+1's
    // 8 loads are already in flight -> the per-warp DRAM request stream never
    // drains to zero (vs. the batch-then-drain pattern).
    float4 a[2][CB_], v[2][CB_];

    // Prologue: load stage 0 into buffer 0.
    #pragma unroll
    for (int i = 0; i < CB_; ++i) {
        a[0][i] = x1p[i * HW4_];
        v[0][i] = __ldcs(&x2p[i * HW4_]);
    }

    #pragma unroll
    for (int s = 0; s < NSTAGE_; ++s) {
        const int cur = s & 1;
        const int nxt = cur ^ 1;

        // Prefetch next stage before consuming current one.
        if (s + 1 < NSTAGE_) {
            const int c0 = (s + 1) * CB_;
            #pragma unroll
            for (int i = 0; i < CB_; ++i) {
                a[nxt][i] = x1p[(c0 + i) * HW4_];
                v[nxt][i] = __ldcs(&x2p[(c0 + i) * HW4_]);
            }
        }

        // Consume current stage.
        #pragma unroll
        for (int i = 0; i < CB_; ++i) {
            float d0 = a[cur][i].x - v[cur][i].x;
            float d1 = a[cur][i].y - v[cur][i].y;
            float d2 = a[cur][i].z - v[cur][i].z;
            float d3 = a[cur][i].w - v[cur][i].w;
            ax = fmaf(d0, d0, ax);
            ay = fmaf(d1, d1, ay);
            az = fmaf(d2, d2, az);
            aw = fmaf(d3, d3, aw);
        }
    }

    float4 r;
    r.x = sqrtf(ax);
    r.y = sqrtf(ay);
    r.z = sqrtf(az);
    r.w = sqrtf(aw);

    reinterpret_cast<float4*>(out)[(size_t)bs * HW4_ + p4] = r;
}

extern "C" void kernel_launch(void* const* d_in, const int* in_sizes, int n_in,
                              void* d_out, int out_size) {
    const float* x1 = (const float*)d_in[0];
    const float* x2 = (const float*)d_in[1];
    float* out = (float*)d_out;

    const int threads = 256;
    const int blocks = (TOTAL_ + threads - 1) / threads;  // 1379, flat grid
    euclidean_block_kernel<<<blocks, threads>>>(x1, x2, out);
}